// round 3
// baseline (speedup 1.0000x reference)
#include <cuda_runtime.h>

#define B_    1024
#define T_    256
#define E_    100
#define H_    128
#define V_    32000
#define ROWS_ (B_ * T_)

#define K1_ROWS 64
#define WPAD    132   // padded stride for transposed W_ih tile (conflict-free, 16B aligned)
#define KC      32    // FC k-chunk
#define SPAD    132   // padded stride for FC smem tiles

// ---------------- scratch (device globals: allocation-free) ----------------
__device__ int   g_is64;
__device__ float g_xp[(size_t)ROWS_ * H_];     // 134 MB: precomputed input projections + biases
__device__ float g_hlast[B_ * H_];             // final hidden state

// ---------------- K0: detect int64 vs int32 indices ----------------
// If x is int64 (values < 32000 => high word 0), every odd int32 word of the
// first 128 elements is 0. If int32, odd words are random values in [0,32000):
// probability all 64 are zero is ~32000^-64 ~ 0.
__global__ void detect_idx_kernel(const int* __restrict__ x32) {
    if (threadIdx.x == 0) {
        int is64 = 1;
        for (int i = 1; i < 256; i += 2) {
            if (x32[i] != 0) { is64 = 0; break; }
        }
        g_is64 = is64;
    }
}

// ---------------- K1: embedding gather + input projection ----------------
// xp[row][j] = sum_e emb[x[row]][e] * W_ih[j][e] + b_ih[j] + b_hh[j]
// Block: 64 rows x 128 cols, 256 threads (tx in [0,32): 4 cols, ty in [0,8): 8 rows)
__global__ void __launch_bounds__(256) embed_proj_kernel(
    const void* __restrict__ xin,
    const float* __restrict__ emb,
    const float* __restrict__ W_ih,
    const float* __restrict__ b_ih,
    const float* __restrict__ b_hh)
{
    extern __shared__ float sm[];
    float* w_sm  = sm;                       // [E_][WPAD] transposed W_ih
    float* e_sm  = sm + E_ * WPAD;           // [K1_ROWS][E_] gathered embeddings
    int*   idx_sm = (int*)(e_sm + K1_ROWS * E_);

    const int tid  = threadIdx.x;
    const int tx   = tid & 31;
    const int ty   = tid >> 5;
    const int row0 = blockIdx.x * K1_ROWS;
    const int is64 = g_is64;

    if (tid < K1_ROWS) {
        int row = row0 + tid;
        long long xi = is64 ? ((const long long*)xin)[row]
                            : (long long)((const int*)xin)[row];
        idx_sm[tid] = (int)xi;
    }
    // load W_ih transposed: w_sm[k][j] = W_ih[j][k]  (coalesced global reads)
    for (int f = tid; f < H_ * E_; f += 256) {
        int j = f / E_, k = f - j * E_;
        w_sm[k * WPAD + j] = W_ih[f];
    }
    __syncthreads();
    // gather embedding rows (emb table is L2-resident: 12.8 MB)
    for (int f = tid; f < K1_ROWS * E_; f += 256) {
        int r = f / E_, k = f - r * E_;
        e_sm[r * E_ + k] = emb[(size_t)idx_sm[r] * E_ + k];
    }
    __syncthreads();

    float4 acc[8];
#pragma unroll
    for (int i = 0; i < 8; i++) acc[i] = make_float4(0.f, 0.f, 0.f, 0.f);

#pragma unroll 5
    for (int c = 0; c < E_ / 4; c++) {
        float4 w0 = *(const float4*)&w_sm[(4 * c + 0) * WPAD + 4 * tx];
        float4 w1 = *(const float4*)&w_sm[(4 * c + 1) * WPAD + 4 * tx];
        float4 w2 = *(const float4*)&w_sm[(4 * c + 2) * WPAD + 4 * tx];
        float4 w3 = *(const float4*)&w_sm[(4 * c + 3) * WPAD + 4 * tx];
#pragma unroll
        for (int i = 0; i < 8; i++) {
            float4 e = *(const float4*)&e_sm[(ty * 8 + i) * E_ + 4 * c];
            acc[i].x += e.x * w0.x + e.y * w1.x + e.z * w2.x + e.w * w3.x;
            acc[i].y += e.x * w0.y + e.y * w1.y + e.z * w2.y + e.w * w3.y;
            acc[i].z += e.x * w0.z + e.y * w1.z + e.z * w2.z + e.w * w3.z;
            acc[i].w += e.x * w0.w + e.y * w1.w + e.z * w2.w + e.w * w3.w;
        }
    }

    float4 bi = *(const float4*)&b_ih[4 * tx];
    float4 bh = *(const float4*)&b_hh[4 * tx];
    float4 bias = make_float4(bi.x + bh.x, bi.y + bh.y, bi.z + bh.z, bi.w + bh.w);
#pragma unroll
    for (int i = 0; i < 8; i++) {
        int row = row0 + ty * 8 + i;
        float4 v = make_float4(acc[i].x + bias.x, acc[i].y + bias.y,
                               acc[i].z + bias.z, acc[i].w + bias.w);
        *(float4*)&g_xp[(size_t)row * H_ + 4 * tx] = v;
    }
}

// ---------------- K2: RNN scan ----------------
// Each block owns 8 independent batch rows. 256 threads: j = tid&127 is the
// output column; half = tid>>7 splits the k-reduction. W_hh lives in REGISTERS
// (64 floats per thread); h is broadcast from smem as float4.
__global__ void __launch_bounds__(256, 1) rnn_kernel(const float* __restrict__ W_hh) {
    __shared__ float h_sm[2][8][H_];
    __shared__ float red[8][H_];

    const int tid  = threadIdx.x;
    const int j    = tid & 127;
    const int half = tid >> 7;          // warp-uniform
    const int b0   = blockIdx.x * 8;

    // W_reg[kk] = W_hh[j][half*64 + kk]   (h_new[j] = sum_k W_hh[j][k] * h[k])
    float W_reg[64];
    {
        const float4* wp = (const float4*)(W_hh + (size_t)j * H_ + half * 64);
#pragma unroll
        for (int q = 0; q < 16; q++) {
            float4 w = wp[q];
            W_reg[4 * q + 0] = w.x; W_reg[4 * q + 1] = w.y;
            W_reg[4 * q + 2] = w.z; W_reg[4 * q + 3] = w.w;
        }
    }
    for (int f = tid; f < 2 * 8 * H_; f += 256) ((float*)h_sm)[f] = 0.f;
    __syncthreads();

    for (int t = 0; t < T_; t++) {
        const int cur = t & 1, nxt = cur ^ 1;

        // prefetch this step's xp early (latency hidden under the FMA loop)
        float xv[8];
        if (half == 0) {
#pragma unroll
            for (int r = 0; r < 8; r++)
                xv[r] = g_xp[((size_t)(b0 + r) * T_ + t) * H_ + j];
        }

        float acc[8];
#pragma unroll
        for (int r = 0; r < 8; r++) acc[r] = 0.f;

#pragma unroll
        for (int c = 0; c < 16; c++) {
#pragma unroll
            for (int r = 0; r < 8; r++) {
                float4 h4 = *(const float4*)&h_sm[cur][r][half * 64 + 4 * c];
                acc[r] += h4.x * W_reg[4 * c + 0] + h4.y * W_reg[4 * c + 1]
                        + h4.z * W_reg[4 * c + 2] + h4.w * W_reg[4 * c + 3];
            }
        }

        if (half == 1) {
#pragma unroll
            for (int r = 0; r < 8; r++) red[r][j] = acc[r];
        }
        __syncthreads();
        if (half == 0) {
#pragma unroll
            for (int r = 0; r < 8; r++) {
                float h = tanhf(acc[r] + red[r][j] + xv[r]);
                h_sm[nxt][r][j] = h;
                if (t == T_ - 1) g_hlast[(b0 + r) * H_ + j] = h;
            }
        }
        __syncthreads();
    }
}

// ---------------- K3: FC head ----------------
// out[b][v] = sum_k h[b][k] * W_fc[v][k] + b_fc[v]
// Classic 128x128 tile, 256 threads, 8x8 micro-tile, K=128 in 32-chunks.
__global__ void __launch_bounds__(256) fc_kernel(
    const float* __restrict__ W_fc,
    const float* __restrict__ b_fc,
    float* __restrict__ out)
{
    __shared__ float As[KC][SPAD];   // [k][m] transposed h tile
    __shared__ float Bs[KC][SPAD];   // [k][n] transposed W_fc tile

    const int tid = threadIdx.x;
    const int tx  = tid & 15;        // 8 cols
    const int ty  = tid >> 4;        // 8 rows
    const int nTile = blockIdx.x * 128;
    const int mTile = blockIdx.y * 128;

    float acc[8][8];
#pragma unroll
    for (int i = 0; i < 8; i++)
#pragma unroll
        for (int jj = 0; jj < 8; jj++) acc[i][jj] = 0.f;

    for (int kc = 0; kc < H_; kc += KC) {
#pragma unroll
        for (int s = 0; s < 4; s++) {
            int f = tid + s * 256;           // 0..1023 -> 128 rows x 8 float4-k
            int m = f >> 3, k4 = f & 7;
            float4 a = *(const float4*)&g_hlast[(size_t)(mTile + m) * H_ + kc + k4 * 4];
            As[k4 * 4 + 0][m] = a.x; As[k4 * 4 + 1][m] = a.y;
            As[k4 * 4 + 2][m] = a.z; As[k4 * 4 + 3][m] = a.w;
            float4 b = *(const float4*)&W_fc[(size_t)(nTile + m) * H_ + kc + k4 * 4];
            Bs[k4 * 4 + 0][m] = b.x; Bs[k4 * 4 + 1][m] = b.y;
            Bs[k4 * 4 + 2][m] = b.z; Bs[k4 * 4 + 3][m] = b.w;
        }
        __syncthreads();
#pragma unroll
        for (int k = 0; k < KC; k++) {
            float4 a0  = *(const float4*)&As[k][ty * 8];
            float4 a1  = *(const float4*)&As[k][ty * 8 + 4];
            float4 bb0 = *(const float4*)&Bs[k][tx * 8];
            float4 bb1 = *(const float4*)&Bs[k][tx * 8 + 4];
            float av[8] = {a0.x, a0.y, a0.z, a0.w, a1.x, a1.y, a1.z, a1.w};
            float bv[8] = {bb0.x, bb0.y, bb0.z, bb0.w, bb1.x, bb1.y, bb1.z, bb1.w};
#pragma unroll
            for (int i = 0; i < 8; i++)
#pragma unroll
                for (int jj = 0; jj < 8; jj++) acc[i][jj] += av[i] * bv[jj];
        }
        __syncthreads();
    }

    float4 p0 = *(const float4*)&b_fc[nTile + tx * 8];
    float4 p1 = *(const float4*)&b_fc[nTile + tx * 8 + 4];
    float bias[8] = {p0.x, p0.y, p0.z, p0.w, p1.x, p1.y, p1.z, p1.w};
#pragma unroll
    for (int i = 0; i < 8; i++) {
        size_t row = (size_t)(mTile + ty * 8 + i);
        float4 v0 = make_float4(acc[i][0] + bias[0], acc[i][1] + bias[1],
                                acc[i][2] + bias[2], acc[i][3] + bias[3]);
        float4 v1 = make_float4(acc[i][4] + bias[4], acc[i][5] + bias[5],
                                acc[i][6] + bias[6], acc[i][7] + bias[7]);
        *(float4*)&out[row * V_ + nTile + tx * 8]     = v0;
        *(float4*)&out[row * V_ + nTile + tx * 8 + 4] = v1;
    }
}

// ---------------- launch ----------------
extern "C" void kernel_launch(void* const* d_in, const int* in_sizes, int n_in,
                              void* d_out, int out_size) {
    const void*  x     = d_in[0];
    const float* emb   = (const float*)d_in[1];
    const float* W_ih  = (const float*)d_in[2];
    const float* W_hh  = (const float*)d_in[3];
    const float* b_ih  = (const float*)d_in[4];
    const float* b_hh  = (const float*)d_in[5];
    const float* W_fc  = (const float*)d_in[6];
    const float* b_fc  = (const float*)d_in[7];
    float* out = (float*)d_out;

    (void)in_sizes; (void)n_in; (void)out_size;

    detect_idx_kernel<<<1, 32>>>((const int*)x);

    const int smem1 = (E_ * WPAD + K1_ROWS * E_) * (int)sizeof(float)
                    + K1_ROWS * (int)sizeof(int);   // 78656 B
    cudaFuncSetAttribute(embed_proj_kernel,
                         cudaFuncAttributeMaxDynamicSharedMemorySize, smem1);
    embed_proj_kernel<<<ROWS_ / K1_ROWS, 256, smem1>>>(x, emb, W_ih, b_ih, b_hh);

    rnn_kernel<<<B_ / 8, 256>>>(W_hh);

    fc_kernel<<<dim3(V_ / 128, B_ / 128), 256>>>(W_fc, b_fc, out);
}

// round 7
// speedup vs baseline: 1.0004x; 1.0004x over previous
#include <cuda_runtime.h>
#include <cstdint>

#define B_    1024
#define T_    256
#define E_    100
#define H_    128
#define V_    32000
#define ROWS_ (B_ * T_)

#define K1_ROWS 64
#define WPAD    132   // padded stride for transposed W_ih tile
#define KC      32    // FC k-chunk

// ---------------- scratch (device globals: allocation-free) ----------------
__device__ int   g_is64;
__device__ float g_xp[(size_t)ROWS_ * H_];     // t-major: [T][B][H]
__device__ float g_hlast[B_ * H_];             // final hidden state [B][H]

// ---------------- cp.async helpers ----------------
#define CP_ASYNC16(dst_u32, src_ptr) \
    asm volatile("cp.async.cg.shared.global [%0], [%1], 16;\n" \
                 :: "r"(dst_u32), "l"(src_ptr))
#define CP_COMMIT() asm volatile("cp.async.commit_group;\n")
#define CP_WAIT(N)  asm volatile("cp.async.wait_group %0;\n" :: "n"(N))

// ---------------- K0: detect int64 vs int32 indices ----------------
// int64 tokens < 32000 => every odd int32 word of first 128 elements is 0.
__global__ void detect_idx_kernel(const int* __restrict__ x32) {
    __shared__ int ok;
    if (threadIdx.x == 0) ok = 1;
    __syncthreads();
    if (x32[2 * threadIdx.x + 1] != 0) ok = 0;
    __syncthreads();
    if (threadIdx.x == 0) g_is64 = ok;
}

// ---------------- K1: embedding gather + input projection ----------------
// xp[t][b][j] = sum_e emb[x[b][t]][e] * W_ih[j][e] + b_ih[j] + b_hh[j]
__global__ void __launch_bounds__(256) embed_proj_kernel(
    const void* __restrict__ xin,
    const float* __restrict__ emb,
    const float* __restrict__ W_ih,
    const float* __restrict__ b_ih,
    const float* __restrict__ b_hh)
{
    extern __shared__ float sm[];
    float* w_sm  = sm;                       // [E_][WPAD] transposed W_ih
    float* e_sm  = sm + E_ * WPAD;           // [K1_ROWS][E_] gathered embeddings
    int*   idx_sm = (int*)(e_sm + K1_ROWS * E_);

    const int tid  = threadIdx.x;
    const int tx   = tid & 31;
    const int ty   = tid >> 5;
    const int row0 = blockIdx.x * K1_ROWS;
    const int is64 = g_is64;

    if (tid < K1_ROWS) {
        int row = row0 + tid;
        long long xi = is64 ? ((const long long*)xin)[row]
                            : (long long)((const int*)xin)[row];
        idx_sm[tid] = (int)xi;
    }
    for (int f = tid; f < H_ * E_; f += 256) {
        int j = f / E_, k = f - j * E_;
        w_sm[k * WPAD + j] = W_ih[f];
    }
    __syncthreads();
    for (int f = tid; f < K1_ROWS * E_; f += 256) {
        int r = f / E_, k = f - r * E_;
        e_sm[r * E_ + k] = emb[(size_t)idx_sm[r] * E_ + k];
    }
    __syncthreads();

    float4 acc[8];
#pragma unroll
    for (int i = 0; i < 8; i++) acc[i] = make_float4(0.f, 0.f, 0.f, 0.f);

#pragma unroll 5
    for (int c = 0; c < E_ / 4; c++) {
        float4 w0 = *(const float4*)&w_sm[(4 * c + 0) * WPAD + 4 * tx];
        float4 w1 = *(const float4*)&w_sm[(4 * c + 1) * WPAD + 4 * tx];
        float4 w2 = *(const float4*)&w_sm[(4 * c + 2) * WPAD + 4 * tx];
        float4 w3 = *(const float4*)&w_sm[(4 * c + 3) * WPAD + 4 * tx];
#pragma unroll
        for (int i = 0; i < 8; i++) {
            float4 e = *(const float4*)&e_sm[(ty * 8 + i) * E_ + 4 * c];
            acc[i].x += e.x * w0.x + e.y * w1.x + e.z * w2.x + e.w * w3.x;
            acc[i].y += e.x * w0.y + e.y * w1.y + e.z * w2.y + e.w * w3.y;
            acc[i].z += e.x * w0.z + e.y * w1.z + e.z * w2.z + e.w * w3.z;
            acc[i].w += e.x * w0.w + e.y * w1.w + e.z * w2.w + e.w * w3.w;
        }
    }

    float4 bi = *(const float4*)&b_ih[4 * tx];
    float4 bh = *(const float4*)&b_hh[4 * tx];
    float4 bias = make_float4(bi.x + bh.x, bi.y + bh.y, bi.z + bh.z, bi.w + bh.w);
#pragma unroll
    for (int i = 0; i < 8; i++) {
        int row = row0 + ty * 8 + i;     // global (b,t): b = row>>8, t = row&255
        int b = row >> 8, t = row & (T_ - 1);
        float4 v = make_float4(acc[i].x + bias.x, acc[i].y + bias.y,
                               acc[i].z + bias.z, acc[i].w + bias.w);
        *(float4*)&g_xp[((size_t)t * B_ + b) * H_ + 4 * tx] = v;
    }
}

// ---------------- K2: RNN scan ----------------
// 128 blocks x 8 rows. j = tid&127 output column, half = tid>>7 splits k.
// W_hh in registers; h broadcast from smem; tail (tanh) split across halves;
// xp prefetched one step ahead into registers.
__global__ void __launch_bounds__(256, 1) rnn_kernel(const float* __restrict__ W_hh) {
    __shared__ float h_sm[8][H_];        // single-buffered hidden state
    __shared__ float red[2][8][H_];      // per-half partial sums

    const int tid   = threadIdx.x;
    const int j     = tid & 127;
    const int half  = tid >> 7;          // warp-uniform
    const int b0    = blockIdx.x * 8;
    const int rbase = half * 4;          // rows this thread finalizes

    float W_reg[64];
    {
        const float4* wp = (const float4*)(W_hh + (size_t)j * H_ + half * 64);
#pragma unroll
        for (int q = 0; q < 16; q++) {
            float4 w = wp[q];
            W_reg[4 * q + 0] = w.x; W_reg[4 * q + 1] = w.y;
            W_reg[4 * q + 2] = w.z; W_reg[4 * q + 3] = w.w;
        }
    }
    for (int f = tid; f < 8 * H_; f += 256) ((float*)h_sm)[f] = 0.f;
    __syncthreads();

    float xv_nxt[4];
#pragma unroll
    for (int i = 0; i < 4; i++)
        xv_nxt[i] = g_xp[(size_t)(b0 + rbase + i) * H_ + j];   // t = 0

    for (int t = 0; t < T_; t++) {
        float xv[4];
#pragma unroll
        for (int i = 0; i < 4; i++) xv[i] = xv_nxt[i];
        if (t + 1 < T_) {
#pragma unroll
            for (int i = 0; i < 4; i++)
                xv_nxt[i] = g_xp[((size_t)(t + 1) * B_ + b0 + rbase + i) * H_ + j];
        }

        float acc[8];
#pragma unroll
        for (int r = 0; r < 8; r++) acc[r] = 0.f;
#pragma unroll
        for (int c = 0; c < 16; c++) {
#pragma unroll
            for (int r = 0; r < 8; r++) {
                float4 h4 = *(const float4*)&h_sm[r][half * 64 + 4 * c];
                acc[r] += h4.x * W_reg[4 * c + 0] + h4.y * W_reg[4 * c + 1]
                        + h4.z * W_reg[4 * c + 2] + h4.w * W_reg[4 * c + 3];
            }
        }

#pragma unroll
        for (int r = 0; r < 8; r++) red[half][r][j] = acc[r];
        __syncthreads();

#pragma unroll
        for (int i = 0; i < 4; i++) {
            int r = rbase + i;
            float s = red[0][r][j] + red[1][r][j] + xv[i];
            s = fminf(fmaxf(s, -15.f), 15.f);
            float e = __expf(2.f * s);
            float h = __fdividef(e - 1.f, e + 1.f);
            h_sm[r][j] = h;
            if (t == T_ - 1) g_hlast[(b0 + r) * H_ + j] = h;
        }
        __syncthreads();
    }
}

// ---------------- K3: FC head ----------------
// out[b][v] = sum_k h[b][k] * W_fc[v][k] + b_fc[v]
// 128x128 tile, 256 threads, 8x8 micro-tile. cp.async double-buffered
// pipeline; k-major tiles with XOR swizzle: sw = k4 ^ ((m>>3)&7).
__device__ __forceinline__ void fc_prefetch(
    uint32_t smA, uint32_t smB,
    const float* __restrict__ hbase, const float* __restrict__ wbase,
    int kc, int tid)
{
#pragma unroll
    for (int s = 0; s < 4; s++) {
        int f  = tid + s * 256;          // 1024 = 128 rows x 8 float4-k
        int m  = f >> 3;
        int k4 = f & 7;
        int sw = k4 ^ ((m >> 3) & 7);
        uint32_t off = (uint32_t)(m * 128 + sw * 16);
        CP_ASYNC16(smA + off, hbase + (size_t)m * H_ + kc + k4 * 4);
        CP_ASYNC16(smB + off, wbase + (size_t)m * H_ + kc + k4 * 4);
    }
}

__global__ void __launch_bounds__(256) fc_kernel(
    const float* __restrict__ W_fc,
    const float* __restrict__ b_fc,
    float* __restrict__ out)
{
    extern __shared__ float sm[];        // [2 stages][A 4096 | B 4096] floats
    const uint32_t sm_u32 = (uint32_t)__cvta_generic_to_shared(sm);

    const int tid = threadIdx.x;
    const int tx  = tid & 15;            // 8 n-cols
    const int ty  = tid >> 4;            // 8 m-rows
    const int nTile = blockIdx.x * 128;
    const int mTile = blockIdx.y * 128;

    const float* hbase = g_hlast + (size_t)mTile * H_;
    const float* wbase = W_fc + (size_t)nTile * H_;

    float acc[8][8];
#pragma unroll
    for (int i = 0; i < 8; i++)
#pragma unroll
        for (int jj = 0; jj < 8; jj++) acc[i][jj] = 0.f;

    fc_prefetch(sm_u32, sm_u32 + 16384, hbase, wbase, 0, tid);
    CP_COMMIT();

    // swizzle base = (m>>3)&7 for the rows this thread reads
    const int aswz_base = ty & 7;        // FIX (R4 bug): was `ty`, ty in [0,16)
    const int bswz_base = tx & 7;

    for (int ch = 0; ch < 4; ch++) {
        if (ch < 3) {
            int st = (ch + 1) & 1;
            fc_prefetch(sm_u32 + st * 32768, sm_u32 + st * 32768 + 16384,
                        hbase, wbase, (ch + 1) * KC, tid);
            CP_COMMIT();
            CP_WAIT(1);
        } else {
            CP_WAIT(0);
        }
        __syncthreads();

        const float* As = sm + (ch & 1) * 8192;
        const float* Bs = As + 4096;

#pragma unroll
        for (int k4 = 0; k4 < 8; k4++) {
            float4 bv[8];
#pragma unroll
            for (int jj = 0; jj < 8; jj++)
                bv[jj] = *(const float4*)&Bs[(tx * 8 + jj) * 32 + (k4 ^ bswz_base) * 4];
#pragma unroll
            for (int i = 0; i < 8; i++) {
                float4 a = *(const float4*)&As[(ty * 8 + i) * 32 + (k4 ^ aswz_base) * 4];
#pragma unroll
                for (int jj = 0; jj < 8; jj++)
                    acc[i][jj] += a.x * bv[jj].x + a.y * bv[jj].y
                                + a.z * bv[jj].z + a.w * bv[jj].w;
            }
        }
        __syncthreads();
    }

    float4 p0 = *(const float4*)&b_fc[nTile + tx * 8];
    float4 p1 = *(const float4*)&b_fc[nTile + tx * 8 + 4];
    float bias[8] = {p0.x, p0.y, p0.z, p0.w, p1.x, p1.y, p1.z, p1.w};
#pragma unroll
    for (int i = 0; i < 8; i++) {
        size_t row = (size_t)(mTile + ty * 8 + i);
        float4 v0 = make_float4(acc[i][0] + bias[0], acc[i][1] + bias[1],
                                acc[i][2] + bias[2], acc[i][3] + bias[3]);
        float4 v1 = make_float4(acc[i][4] + bias[4], acc[i][5] + bias[5],
                                acc[i][6] + bias[6], acc[i][7] + bias[7]);
        *(float4*)&out[row * V_ + nTile + tx * 8]     = v0;
        *(float4*)&out[row * V_ + nTile + tx * 8 + 4] = v1;
    }
}

// ---------------- launch ----------------
extern "C" void kernel_launch(void* const* d_in, const int* in_sizes, int n_in,
                              void* d_out, int out_size) {
    const void*  x     = d_in[0];
    const float* emb   = (const float*)d_in[1];
    const float* W_ih  = (const float*)d_in[2];
    const float* W_hh  = (const float*)d_in[3];
    const float* b_ih  = (const float*)d_in[4];
    const float* b_hh  = (const float*)d_in[5];
    const float* W_fc  = (const float*)d_in[6];
    const float* b_fc  = (const float*)d_in[7];
    float* out = (float*)d_out;

    (void)in_sizes; (void)n_in; (void)out_size;

    detect_idx_kernel<<<1, 128>>>((const int*)x);

    const int smem1 = (E_ * WPAD + K1_ROWS * E_) * (int)sizeof(float)
                    + K1_ROWS * (int)sizeof(int);   // 78656 B
    cudaFuncSetAttribute(embed_proj_kernel,
                         cudaFuncAttributeMaxDynamicSharedMemorySize, smem1);
    embed_proj_kernel<<<ROWS_ / K1_ROWS, 256, smem1>>>(x, emb, W_ih, b_ih, b_hh);

    rnn_kernel<<<B_ / 8, 256>>>(W_hh);

    const int smem3 = 2 * 2 * 4096 * (int)sizeof(float);   // 65536 B
    cudaFuncSetAttribute(fc_kernel,
                         cudaFuncAttributeMaxDynamicSharedMemorySize, smem3);
    fc_kernel<<<dim3(V_ / 128, B_ / 128), 256, smem3>>>(W_fc, b_fc, out);
}

// round 8
// speedup vs baseline: 1.0641x; 1.0637x over previous
#include <cuda_runtime.h>
#include <cstdint>

#define B_    1024
#define T_    256
#define E_    100
#define H_    128
#define V_    32000
#define ROWS_ (B_ * T_)

#define K1_ROWS 64
#define WPAD    132   // padded stride for transposed W_ih tile
#define KC      32    // FC k-chunk

// ---------------- scratch (device globals: allocation-free) ----------------
__device__ int   g_is64;
__device__ float g_xp[(size_t)ROWS_ * H_];     // t-major: [T][B][H]
__device__ float g_hlast[B_ * H_];             // final hidden state [B][H]

// ---------------- cp.async helpers ----------------
#define CP_ASYNC16(dst_u32, src_ptr) \
    asm volatile("cp.async.cg.shared.global [%0], [%1], 16;\n" \
                 :: "r"(dst_u32), "l"(src_ptr))
#define CP_COMMIT() asm volatile("cp.async.commit_group;\n")
#define CP_WAIT(N)  asm volatile("cp.async.wait_group %0;\n" :: "n"(N))

// ---------------- K0: detect int64 vs int32 indices ----------------
__global__ void detect_idx_kernel(const int* __restrict__ x32) {
    __shared__ int ok;
    if (threadIdx.x == 0) ok = 1;
    __syncthreads();
    if (x32[2 * threadIdx.x + 1] != 0) ok = 0;
    __syncthreads();
    if (threadIdx.x == 0) g_is64 = ok;
}

// ---------------- K1: embedding gather + input projection ----------------
// xp[t][b][j] = sum_e emb[x[b][t]][e] * W_ih[j][e] + b_ih[j] + b_hh[j]
__global__ void __launch_bounds__(256) embed_proj_kernel(
    const void* __restrict__ xin,
    const float* __restrict__ emb,
    const float* __restrict__ W_ih,
    const float* __restrict__ b_ih,
    const float* __restrict__ b_hh)
{
    extern __shared__ float sm[];
    float* w_sm  = sm;                       // [E_][WPAD] transposed W_ih
    float* e_sm  = sm + E_ * WPAD;           // [K1_ROWS][E_] gathered embeddings
    int*   idx_sm = (int*)(e_sm + K1_ROWS * E_);

    const int tid  = threadIdx.x;
    const int tx   = tid & 31;
    const int ty   = tid >> 5;
    const int row0 = blockIdx.x * K1_ROWS;
    const int is64 = g_is64;

    if (tid < K1_ROWS) {
        int row = row0 + tid;
        long long xi = is64 ? ((const long long*)xin)[row]
                            : (long long)((const int*)xin)[row];
        idx_sm[tid] = (int)xi;
    }
    for (int f = tid; f < H_ * E_; f += 256) {
        int j = f / E_, k = f - j * E_;
        w_sm[k * WPAD + j] = W_ih[f];
    }
    __syncthreads();
    for (int f = tid; f < K1_ROWS * E_; f += 256) {
        int r = f / E_, k = f - r * E_;
        e_sm[r * E_ + k] = emb[(size_t)idx_sm[r] * E_ + k];
    }
    __syncthreads();

    float4 acc[8];
#pragma unroll
    for (int i = 0; i < 8; i++) acc[i] = make_float4(0.f, 0.f, 0.f, 0.f);

#pragma unroll 5
    for (int c = 0; c < E_ / 4; c++) {
        float4 w0 = *(const float4*)&w_sm[(4 * c + 0) * WPAD + 4 * tx];
        float4 w1 = *(const float4*)&w_sm[(4 * c + 1) * WPAD + 4 * tx];
        float4 w2 = *(const float4*)&w_sm[(4 * c + 2) * WPAD + 4 * tx];
        float4 w3 = *(const float4*)&w_sm[(4 * c + 3) * WPAD + 4 * tx];
#pragma unroll
        for (int i = 0; i < 8; i++) {
            float4 e = *(const float4*)&e_sm[(ty * 8 + i) * E_ + 4 * c];
            acc[i].x += e.x * w0.x + e.y * w1.x + e.z * w2.x + e.w * w3.x;
            acc[i].y += e.x * w0.y + e.y * w1.y + e.z * w2.y + e.w * w3.y;
            acc[i].z += e.x * w0.z + e.y * w1.z + e.z * w2.z + e.w * w3.z;
            acc[i].w += e.x * w0.w + e.y * w1.w + e.z * w2.w + e.w * w3.w;
        }
    }

    float4 bi = *(const float4*)&b_ih[4 * tx];
    float4 bh = *(const float4*)&b_hh[4 * tx];
    float4 bias = make_float4(bi.x + bh.x, bi.y + bh.y, bi.z + bh.z, bi.w + bh.w);
#pragma unroll
    for (int i = 0; i < 8; i++) {
        int row = row0 + ty * 8 + i;     // global (b,t): b = row>>8, t = row&255
        int b = row >> 8, t = row & (T_ - 1);
        float4 v = make_float4(acc[i].x + bias.x, acc[i].y + bias.y,
                               acc[i].z + bias.z, acc[i].w + bias.w);
        *(float4*)&g_xp[((size_t)t * B_ + b) * H_ + 4 * tx] = v;
    }
}

// ---------------- K2: RNN scan (512 threads: 4 warps/SMSP) ----------------
// 128 blocks x 8 rows. j = tid&127 output column, q = tid>>7 is the k-quarter.
// W_hh quarter in registers (32 floats); h broadcast from smem (warp-uniform
// addresses -> conflict-free); 4-way reduction through smem; tail rows 2q,2q+1.
__global__ void __launch_bounds__(512, 1) rnn_kernel(const float* __restrict__ W_hh) {
    __shared__ float h_sm[8][H_];        // hidden state (single-buffered)
    __shared__ float red[4][8][H_];      // per-quarter partial sums

    const int tid = threadIdx.x;
    const int j   = tid & 127;
    const int q   = tid >> 7;            // 0..3, warp-uniform
    const int b0  = blockIdx.x * 8;
    const int r0  = q * 2;               // rows this thread finalizes

    float W_reg[32];
    {
        const float4* wp = (const float4*)(W_hh + (size_t)j * H_ + q * 32);
#pragma unroll
        for (int p = 0; p < 8; p++) {
            float4 w = wp[p];
            W_reg[4 * p + 0] = w.x; W_reg[4 * p + 1] = w.y;
            W_reg[4 * p + 2] = w.z; W_reg[4 * p + 3] = w.w;
        }
    }
    for (int f = tid; f < 8 * H_; f += 512) ((float*)h_sm)[f] = 0.f;
    __syncthreads();

    float xv_nxt[2];
#pragma unroll
    for (int i = 0; i < 2; i++)
        xv_nxt[i] = g_xp[(size_t)(b0 + r0 + i) * H_ + j];   // t = 0

    for (int t = 0; t < T_; t++) {
        float xv[2];
        xv[0] = xv_nxt[0]; xv[1] = xv_nxt[1];
        if (t + 1 < T_) {
#pragma unroll
            for (int i = 0; i < 2; i++)
                xv_nxt[i] = g_xp[((size_t)(t + 1) * B_ + b0 + r0 + i) * H_ + j];
        }

        float acc[8];
#pragma unroll
        for (int r = 0; r < 8; r++) acc[r] = 0.f;
#pragma unroll
        for (int c = 0; c < 8; c++) {
#pragma unroll
            for (int r = 0; r < 8; r++) {
                float4 h4 = *(const float4*)&h_sm[r][q * 32 + 4 * c];
                acc[r] += h4.x * W_reg[4 * c + 0] + h4.y * W_reg[4 * c + 1]
                        + h4.z * W_reg[4 * c + 2] + h4.w * W_reg[4 * c + 3];
            }
        }

#pragma unroll
        for (int r = 0; r < 8; r++) red[q][r][j] = acc[r];
        __syncthreads();

#pragma unroll
        for (int i = 0; i < 2; i++) {
            int r = r0 + i;
            float s = red[0][r][j] + red[1][r][j]
                    + red[2][r][j] + red[3][r][j] + xv[i];
            s = fminf(fmaxf(s, -15.f), 15.f);
            float e = __expf(2.f * s);
            float h = __fdividef(e - 1.f, e + 1.f);
            h_sm[r][j] = h;
            if (t == T_ - 1) g_hlast[(b0 + r) * H_ + j] = h;
        }
        __syncthreads();
    }
}

// ---------------- K3: FC head ----------------
// out[b][v] = sum_k h[b][k] * W_fc[v][k] + b_fc[v]
// 128x128 tile, 256 threads, 8x8 micro-tile, cp.async double-buffer,
// XOR-swizzled k-major tiles. __launch_bounds__(256,2): 2 blocks/SM.
__device__ __forceinline__ void fc_prefetch(
    uint32_t smA, uint32_t smB,
    const float* __restrict__ hbase, const float* __restrict__ wbase,
    int kc, int tid)
{
#pragma unroll
    for (int s = 0; s < 4; s++) {
        int f  = tid + s * 256;          // 1024 = 128 rows x 8 float4-k
        int m  = f >> 3;
        int k4 = f & 7;
        int sw = k4 ^ ((m >> 3) & 7);
        uint32_t off = (uint32_t)(m * 128 + sw * 16);
        CP_ASYNC16(smA + off, hbase + (size_t)m * H_ + kc + k4 * 4);
        CP_ASYNC16(smB + off, wbase + (size_t)m * H_ + kc + k4 * 4);
    }
}

__global__ void __launch_bounds__(256, 2) fc_kernel(
    const float* __restrict__ W_fc,
    const float* __restrict__ b_fc,
    float* __restrict__ out)
{
    extern __shared__ float sm[];        // [2 stages][A 4096 | B 4096] floats
    const uint32_t sm_u32 = (uint32_t)__cvta_generic_to_shared(sm);

    const int tid = threadIdx.x;
    const int tx  = tid & 15;            // 8 n-cols
    const int ty  = tid >> 4;            // 8 m-rows
    const int nTile = blockIdx.x * 128;
    const int mTile = blockIdx.y * 128;

    const float* hbase = g_hlast + (size_t)mTile * H_;
    const float* wbase = W_fc + (size_t)nTile * H_;

    float acc[8][8];
#pragma unroll
    for (int i = 0; i < 8; i++)
#pragma unroll
        for (int jj = 0; jj < 8; jj++) acc[i][jj] = 0.f;

    fc_prefetch(sm_u32, sm_u32 + 16384, hbase, wbase, 0, tid);
    CP_COMMIT();

    const int aswz_base = ty & 7;
    const int bswz_base = tx & 7;

    for (int ch = 0; ch < 4; ch++) {
        if (ch < 3) {
            int st = (ch + 1) & 1;
            fc_prefetch(sm_u32 + st * 32768, sm_u32 + st * 32768 + 16384,
                        hbase, wbase, (ch + 1) * KC, tid);
            CP_COMMIT();
            CP_WAIT(1);
        } else {
            CP_WAIT(0);
        }
        __syncthreads();

        const float* As = sm + (ch & 1) * 8192;
        const float* Bs = As + 4096;

#pragma unroll
        for (int k4 = 0; k4 < 8; k4++) {
            float4 bv[8];
#pragma unroll
            for (int jj = 0; jj < 8; jj++)
                bv[jj] = *(const float4*)&Bs[(tx * 8 + jj) * 32 + (k4 ^ bswz_base) * 4];
#pragma unroll
            for (int i = 0; i < 8; i++) {
                float4 a = *(const float4*)&As[(ty * 8 + i) * 32 + (k4 ^ aswz_base) * 4];
#pragma unroll
                for (int jj = 0; jj < 8; jj++)
                    acc[i][jj] += a.x * bv[jj].x + a.y * bv[jj].y
                                + a.z * bv[jj].z + a.w * bv[jj].w;
            }
        }
        __syncthreads();
    }

    float4 p0 = *(const float4*)&b_fc[nTile + tx * 8];
    float4 p1 = *(const float4*)&b_fc[nTile + tx * 8 + 4];
    float bias[8] = {p0.x, p0.y, p0.z, p0.w, p1.x, p1.y, p1.z, p1.w};
#pragma unroll
    for (int i = 0; i < 8; i++) {
        size_t row = (size_t)(mTile + ty * 8 + i);
        float4 v0 = make_float4(acc[i][0] + bias[0], acc[i][1] + bias[1],
                                acc[i][2] + bias[2], acc[i][3] + bias[3]);
        float4 v1 = make_float4(acc[i][4] + bias[4], acc[i][5] + bias[5],
                                acc[i][6] + bias[6], acc[i][7] + bias[7]);
        *(float4*)&out[row * V_ + nTile + tx * 8]     = v0;
        *(float4*)&out[row * V_ + nTile + tx * 8 + 4] = v1;
    }
}

// ---------------- launch ----------------
extern "C" void kernel_launch(void* const* d_in, const int* in_sizes, int n_in,
                              void* d_out, int out_size) {
    const void*  x     = d_in[0];
    const float* emb   = (const float*)d_in[1];
    const float* W_ih  = (const float*)d_in[2];
    const float* W_hh  = (const float*)d_in[3];
    const float* b_ih  = (const float*)d_in[4];
    const float* b_hh  = (const float*)d_in[5];
    const float* W_fc  = (const float*)d_in[6];
    const float* b_fc  = (const float*)d_in[7];
    float* out = (float*)d_out;

    (void)in_sizes; (void)n_in; (void)out_size;

    detect_idx_kernel<<<1, 128>>>((const int*)x);

    const int smem1 = (E_ * WPAD + K1_ROWS * E_) * (int)sizeof(float)
                    + K1_ROWS * (int)sizeof(int);   // 78656 B
    cudaFuncSetAttribute(embed_proj_kernel,
                         cudaFuncAttributeMaxDynamicSharedMemorySize, smem1);
    embed_proj_kernel<<<ROWS_ / K1_ROWS, 256, smem1>>>(x, emb, W_ih, b_ih, b_hh);

    rnn_kernel<<<B_ / 8, 512>>>(W_hh);

    const int smem3 = 2 * 2 * 4096 * (int)sizeof(float);   // 65536 B
    cudaFuncSetAttribute(fc_kernel,
                         cudaFuncAttributeMaxDynamicSharedMemorySize, smem3);
    fc_kernel<<<dim3(V_ / 128, B_ / 128), 256, smem3>>>(W_fc, b_fc, out);
}